// round 7
// baseline (speedup 1.0000x reference)
#include <cuda_runtime.h>
#include <cstdint>

#define N_BOX 16384
#define FEAT 512
#define NUM_CATS 65
#define KSEL 25
#define MAX_DETS 1000
#define NMS_THRESH 0.6f
#define MIN_RPN 0.9f
#define MIN_AREA 220.0f
#define FLAG_WORDS 512      /* 16384/32 */
#define CAP 4096            /* hard cap on boxes passing score gate */
#define RW  (CAP / 32)      /* 128 words per matrix row */

// ---------------- device scratch ----------------
__device__ int    g_M;
__device__ int    g_sortedIdx[CAP];
__device__ float4 g_sortedBox[CAP];
__device__ float  g_areaArr[CAP];
__device__ unsigned g_mat[(size_t)CAP * RW];   // suppression bitmask, words w >= i>>5 (bits j>i)

typedef unsigned long long u64;

// ================= kernel 1: compact + hybrid bitonic sort + gather =================
__device__ __forceinline__ u64 shflCmp(u64 v, int halfj, bool up, int tid) {
    u64 o = __shfl_xor_sync(0xffffffffu, v, halfj);
    bool lower = ((tid & halfj) == 0);
    bool keepSmall = (lower == up);
    return keepSmall ? (v < o ? v : o) : (v > o ? v : o);
}
__device__ __forceinline__ void cmpSwapReg(u64 &a, u64 &b, bool up) {
    u64 lo = a < b ? a : b, hi = a < b ? b : a;
    a = up ? lo : hi;  b = up ? hi : lo;
}
__device__ __forceinline__ void writeOut(u64 key, int e, int M,
                                         const float* __restrict__ det_boxes) {
    if (e < M) {
        int orig = (int)(key & 0xFFFFFFFFu);
        g_sortedIdx[e] = orig;
        float4 b = ((const float4*)det_boxes)[orig];   // [y1, x1, y2, x2]
        g_sortedBox[e] = b;
        g_areaArr[e] = (b.w - b.y) * (b.z - b.x);      // (x2-x1)*(y2-y1)
    }
}

__global__ __launch_bounds__(1024, 1)
void kPrep(const float* __restrict__ roi_scores,
           const float* __restrict__ det_boxes) {
    extern __shared__ u64 sKeys[];                     // CAP entries = 32 KB
    __shared__ int s_cnt;
    const int tid = threadIdx.x;
    const u64 PADK = 0xFFFFFFFFFFFFFFFFULL;
    if (tid == 0) s_cnt = 0;
    __syncthreads();

    for (int i = tid; i < N_BOX; i += 1024) {
        float s = roi_scores[i];
        if (s >= MIN_RPN) {
            int p = atomicAdd(&s_cnt, 1);
            if (p < CAP)
                sKeys[p] = ((u64)(0xFFFFFFFFu - __float_as_uint(s)) << 32) | (unsigned)i;
        }
    }
    __syncthreads();
    const int M = min(s_cnt, CAP);
    if (tid == 0) g_M = M;

    if (M <= 2048) {
        // ---------- fast path: P=2048, hybrid shared/register bitonic ----------
        for (int t = M + tid; t < 2048; t += 1024) sKeys[t] = PADK;
        __syncthreads();
        u64 a = sKeys[2 * tid], b = sKeys[2 * tid + 1];

        // phases k=2..32: fully in registers/warp shuffles (no barriers)
        #pragma unroll
        for (int k = 2; k <= 32; k <<= 1) {
            bool up = ((tid & (k >> 1)) == 0);
            for (int j = k >> 1; j >= 2; j >>= 1) {
                a = shflCmp(a, j >> 1, up, tid);
                b = shflCmp(b, j >> 1, up, tid);
            }
            cmpSwapReg(a, b, up);
        }
        // phases k=64..2048: shared stages for j>=32, register stages for j<=16
        for (int k = 64; k <= 2048; k <<= 1) {
            sKeys[2 * tid] = a; sKeys[2 * tid + 1] = b;
            __syncthreads();
            for (int j = k >> 1; j >= 32; j >>= 1) {
                #pragma unroll
                for (int r = 0; r < 2; ++r) {
                    int t2 = tid + r * 1024;
                    int ixj = t2 ^ j;
                    if (ixj > t2) {
                        bool up2 = ((t2 & k) == 0);
                        u64 x = sKeys[t2], y = sKeys[ixj];
                        if ((x > y) == up2) { sKeys[t2] = y; sKeys[ixj] = x; }
                    }
                }
                __syncthreads();
            }
            a = sKeys[2 * tid]; b = sKeys[2 * tid + 1];
            bool up = ((tid & (k >> 1)) == 0);
            #pragma unroll
            for (int j = 16; j >= 2; j >>= 1) {
                a = shflCmp(a, j >> 1, up, tid);
                b = shflCmp(b, j >> 1, up, tid);
            }
            cmpSwapReg(a, b, up);
        }
        writeOut(a, 2 * tid,     M, det_boxes);
        writeOut(b, 2 * tid + 1, M, det_boxes);
    } else {
        // ---------- generic fallback: shared-only bitonic up to P=4096 ----------
        int P = 2; while (P < M) P <<= 1;
        for (int t = M + tid; t < P; t += 1024) sKeys[t] = PADK;
        __syncthreads();
        for (int k = 2; k <= P; k <<= 1) {
            for (int j = k >> 1; j > 0; j >>= 1) {
                for (int t = tid; t < P; t += 1024) {
                    int ixj = t ^ j;
                    if (ixj > t) {
                        bool up = ((t & k) == 0);
                        u64 x = sKeys[t], y = sKeys[ixj];
                        if ((x > y) == up) { sKeys[t] = y; sKeys[ixj] = x; }
                    }
                }
                __syncthreads();
            }
        }
        for (int t = tid; t < M; t += 1024) writeOut(sKeys[t], t, M, det_boxes);
    }
}

// ================= kernel 2: triangular suppression bitmask (incl. diagonal words) =================
__global__ void kMatrix() {
    const int M  = g_M;
    const int Mw = (M + 31) >> 5;
    const int total = M * Mw;
    const int stride = gridDim.x * blockDim.x;
    for (int it = blockIdx.x * blockDim.x + threadIdx.x; it < total; it += stride) {
        int i = it / Mw;
        int w = it - i * Mw;
        if (w < (i >> 5)) continue;          // words w >= i>>5; bits restricted to j > i
        float4 bi = g_sortedBox[i];
        float  ai = g_areaArr[i];
        unsigned bits = 0;
        int j0 = w * 32;
        int jend = min(32, M - j0);
        int jstart = (j0 <= i) ? (i - j0 + 1) : 0;   // diagonal word: only j > i
        for (int jj = jstart; jj < jend; ++jj) {
            float4 bj = g_sortedBox[j0 + jj];
            float iw = fmaxf(0.0f, fminf(bi.w, bj.w) - fmaxf(bi.y, bj.y));
            float ih = fmaxf(0.0f, fminf(bi.z, bj.z) - fmaxf(bi.x, bj.x));
            float inter = iw * ih;
            float iou = inter / (ai + g_areaArr[j0 + jj] - inter + 1e-12f);
            if (iou > NMS_THRESH) bits |= (1u << jj);
        }
        g_mat[(size_t)i * RW + w] = bits;
    }
}

// ================= kernel 3: barrier-free scan + select + GEMM + sort + outputs =================
#define NTHR 512

__global__ __launch_bounds__(NTHR, 1)
void kFinal(const float* __restrict__ roi_boxes,
            const float* __restrict__ det_boxes,
            const float* __restrict__ vis,
            const float* __restrict__ img_info,
            const float* __restrict__ txt,
            float* __restrict__ out) {
    __shared__ unsigned s_keepw[RW];
    __shared__ unsigned s_flags[FLAG_WORDS];
    __shared__ int      s_scan[FLAG_WORDS];
    __shared__ int      s_wsum[16];
    __shared__ int      s_count;
    __shared__ int      s_selidx[KSEL];
    __shared__ float    S[KSEL][NUM_CATS];
    __shared__ float    s_key[KSEL];
    __shared__ int      s_src[KSEL];
    __shared__ unsigned char s_fgv[KSEL];

    const int tid  = threadIdx.x;
    const int lane = tid & 31;
    const int wid  = tid >> 5;          // 16 warps
    const int M    = g_M;
    const int Mw   = (M + 31) >> 5;

    for (int t = tid; t < RW; t += NTHR) s_keepw[t] = 0;
    for (int t = tid; t < FLAG_WORDS; t += NTHR) s_flags[t] = 0;
    __syncthreads();

    // ---- single-warp, barrier-free greedy NMS scan ----
    if (wid == 0) {
        unsigned rw0 = 0, rw1 = 0, rw2 = 0, rw3 = 0;   // removed word (lane + 32*s)
        int cnt = 0;
        // prefetch diagonal word for chunk 0
        unsigned diag = 0;
        if (Mw > 0 && lane < min(32, M))
            diag = g_mat[(size_t)lane * RW + 0];

        for (int c = 0; c < Mw; ++c) {
            const int base = c * 32;
            const int lim  = min(32, M - base);
            const unsigned valid = (lim >= 32) ? 0xFFFFFFFFu : ((1u << lim) - 1u);

            // fetch this chunk's removed word (register-distributed)
            unsigned slotv = (c < 32) ? rw0 : (c < 64) ? rw1 : (c < 96) ? rw2 : rw3;
            unsigned remAll = __shfl_sync(0xFFFFFFFFu, slotv, c & 31);

            // prefetch next chunk's diagonal word (hide L2 latency under resolve)
            unsigned nextdiag = 0;
            if (c + 1 < Mw) {
                int nb = (c + 1) * 32;
                if (lane < min(32, M - nb))
                    nextdiag = g_mat[(size_t)(nb + lane) * RW + (c + 1)];
            }

            // leader resolve: all lanes lockstep & uniform
            unsigned km = 0;
            unsigned avail = valid & ~remAll;
            while (avail && cnt < MAX_DETS) {
                int i = __ffs(avail) - 1;
                km |= 1u << i;
                ++cnt;
                unsigned row = __shfl_sync(0xFFFFFFFFu, diag, i);
                avail &= ~(row | (1u << i));
            }
            if (lane == 0) s_keepw[c] = km;

            // cross-chunk update: lane owns words w = lane + 32*s
            if (km) {
                #pragma unroll
                for (int s = 0; s < 4; ++s) {
                    int w = lane + 32 * s;
                    unsigned acc = 0;
                    if (w > c && w < Mw) {
                        #pragma unroll
                        for (int i2 = 0; i2 < 32; ++i2) {
                            if ((km >> i2) & 1u)
                                acc |= g_mat[(size_t)(base + i2) * RW + w];
                        }
                    }
                    if (s == 0) rw0 |= acc; else if (s == 1) rw1 |= acc;
                    else if (s == 2) rw2 |= acc; else rw3 |= acc;
                }
            }
            diag = nextdiag;
            if (cnt >= MAX_DETS) break;     // later chunks keep nothing (s_keepw stays 0)
        }
    }
    __syncthreads();

    // ---- valid flags on ORIGINAL indices ----
    const float sy = img_info[4];    // image_info[2][0]
    const float sx = img_info[5];    // image_info[2][1]
    for (int t = tid; t < M; t += NTHR) {
        if ((s_keepw[t >> 5] >> (t & 31)) & 1u) {
            int orig = g_sortedIdx[t];
            float4 rb = ((const float4*)roi_boxes)[orig];
            bool allz = (rb.x == 0.f && rb.y == 0.f && rb.z == 0.f && rb.w == 0.f);
            float4 db = g_sortedBox[t];
            float area = (db.z / sy - db.x / sy) * (db.w / sx - db.y / sx);
            if (!allz && area > MIN_AREA)
                atomicOr(&s_flags[orig >> 5], 1u << (orig & 31));
        }
    }
    __syncthreads();

    // ---- inclusive prefix scan over 512 popcounts (warp shuffles) ----
    {
        int v = __popc(s_flags[tid]);
        #pragma unroll
        for (int off = 1; off < 32; off <<= 1) {
            int n = __shfl_up_sync(0xffffffff, v, off);
            if (lane >= off) v += n;
        }
        if (lane == 31) s_wsum[wid] = v;
        __syncthreads();
        if (wid == 0 && lane < 16) {
            int w = s_wsum[lane];
            #pragma unroll
            for (int off = 1; off < 16; off <<= 1) {
                int n = __shfl_up_sync(0x0000ffff, w, off);
                if (lane >= off) w += n;
            }
            s_wsum[lane] = w;
        }
        __syncthreads();
        int basew = (wid > 0) ? s_wsum[wid - 1] : 0;
        s_scan[tid] = basew + v;                         // inclusive
        if (tid == 0) s_count = s_wsum[15];
    }
    if (tid < KSEL) s_selidx[tid] = 0;                   // jnp.nonzero fill_value = 0
    __syncthreads();
    {
        int excl = s_scan[tid] - __popc(s_flags[tid]);
        if (excl < KSEL) {
            unsigned f = s_flags[tid];
            int r = excl;
            while (f && r < KSEL) {
                int b = __ffs(f) - 1; f &= f - 1;
                s_selidx[r] = tid * 32 + b;
                ++r;
            }
        }
    }
    __syncthreads();

    // ---- GEMM: S[25][65] = vis[idx] @ txt^T  (warp-per-2-rows, K split across lanes) ----
    if (wid < 13) {
        const int r0 = 2 * wid;
        const int r1 = r0 + 1;
        const bool has1 = (r1 < KSEL);
        const float4* v0 = (const float4*)(vis + (size_t)s_selidx[r0] * FEAT);
        const float4* v1 = (const float4*)(vis + (size_t)s_selidx[has1 ? r1 : r0] * FEAT);
        float4 a0[4], a1[4];
        #pragma unroll
        for (int q = 0; q < 4; ++q) {
            a0[q] = v0[q * 32 + lane];                   // coalesced: 32 lanes = 512B
            a1[q] = v1[q * 32 + lane];
        }
        for (int cc = 0; cc < NUM_CATS; ++cc) {
            const float4* tf = (const float4*)(txt + (size_t)cc * FEAT);
            float p0 = 0.f, p1 = 0.f;
            #pragma unroll
            for (int q = 0; q < 4; ++q) {
                float4 b = tf[q * 32 + lane];            // coalesced
                p0 += a0[q].x * b.x + a0[q].y * b.y + a0[q].z * b.z + a0[q].w * b.w;
                p1 += a1[q].x * b.x + a1[q].y * b.y + a1[q].z * b.z + a1[q].w * b.w;
            }
            #pragma unroll
            for (int off = 16; off; off >>= 1) {
                p0 += __shfl_xor_sync(0xffffffff, p0, off);
                p1 += __shfl_xor_sync(0xffffffff, p1, off);
            }
            if (lane == 0) {
                S[r0][cc] = p0;
                if (has1) S[r1][cc] = p1;
            }
        }
    }
    __syncthreads();

    // ---- per-row max / argmax, fg, sort key ----
    if (tid < KSEL) {
        float mx = S[tid][0]; int am = 0;
        for (int cc = 1; cc < NUM_CATS; ++cc) {
            float v = S[tid][cc];
            if (v > mx) { mx = v; am = cc; }
        }
        bool rv = tid < min(s_count, KSEL);
        bool fg = rv && (am != 0);
        s_fgv[tid] = fg ? 1 : 0;
        s_key[tid] = fg ? mx : __int_as_float(0xff800000);   // -inf
    }
    __syncthreads();

    // ---- stable descending argsort via rank ----
    if (tid < KSEL) {
        float k = s_key[tid];
        int rank = 0;
        for (int j = 0; j < KSEL; ++j) {
            float kj = s_key[j];
            if (kj > k || (kj == k && j < tid)) ++rank;
        }
        s_src[rank] = tid;
    }
    __syncthreads();

    // ---- outputs: scores (25x64) | bboxes (25x4) | mask (25) ----
    for (int p = tid; p < KSEL * (NUM_CATS - 1); p += NTHR) {
        int row = p / (NUM_CATS - 1), cc = p - row * (NUM_CATS - 1);
        int s = s_src[row];
        out[p] = s_fgv[s] ? S[s][cc + 1] : 0.f;
    }
    if (tid < KSEL) {
        int s = s_src[tid];
        bool m = s_fgv[s] != 0;
        float4 db = ((const float4*)det_boxes)[s_selidx[s]];
        float xmin = db.y / sx, ymin = db.x / sy, xmax = db.w / sx, ymax = db.z / sy;
        float* o = out + KSEL * (NUM_CATS - 1) + tid * 4;
        o[0] = m ? xmin : 0.f;
        o[1] = m ? ymin : 0.f;
        o[2] = m ? xmax : 0.f;
        o[3] = m ? ymax : 0.f;
        out[KSEL * (NUM_CATS - 1) + KSEL * 4 + tid] = m ? 1.f : 0.f;
    }
}

// ---------------- launch ----------------
extern "C" void kernel_launch(void* const* d_in, const int* in_sizes, int n_in,
                              void* d_out, int out_size) {
    const float* roi_boxes  = (const float*)d_in[0];
    const float* roi_scores = (const float*)d_in[1];
    const float* det_boxes  = (const float*)d_in[2];
    /* d_in[3]: detection_masks — unused by reference outputs */
    const float* vis        = (const float*)d_in[4];
    const float* img_info   = (const float*)d_in[5];
    const float* txt        = (const float*)d_in[6];
    float* out = (float*)d_out;

    kPrep<<<1, 1024, CAP * 8>>>(roi_scores, det_boxes);
    kMatrix<<<512, 256>>>();
    kFinal<<<1, NTHR>>>(roi_boxes, det_boxes, vis, img_info, txt, out);
}

// round 8
// speedup vs baseline: 2.1012x; 2.1012x over previous
#include <cuda_runtime.h>
#include <cstdint>

#define N_BOX 16384
#define FEAT 512
#define NUM_CATS 65
#define KSEL 25
#define MAX_DETS 1000
#define NMS_THRESH 0.6f
#define MIN_RPN 0.9f
#define MIN_AREA 220.0f
#define FLAG_WORDS 512      /* 16384/32 */
#define CAP 4096            /* hard cap on boxes passing score gate */
#define RW  (CAP / 32)      /* 128 words per matrix row */

// ---------------- device scratch ----------------
__device__ int    g_M;
__device__ int    g_sortedIdx[CAP];
__device__ float4 g_sortedBox[CAP];
__device__ float  g_areaArr[CAP];
__device__ unsigned g_mat[(size_t)CAP * RW];   // suppression bitmask, words w >= i>>5 (bits j>i)

typedef unsigned long long u64;

// ================= kernel 1: compact + hybrid bitonic sort + gather =================
__device__ __forceinline__ u64 shflCmp(u64 v, int halfj, bool up, int tid) {
    u64 o = __shfl_xor_sync(0xffffffffu, v, halfj);
    bool lower = ((tid & halfj) == 0);
    bool keepSmall = (lower == up);
    return keepSmall ? (v < o ? v : o) : (v > o ? v : o);
}
__device__ __forceinline__ void cmpSwapReg(u64 &a, u64 &b, bool up) {
    u64 lo = a < b ? a : b, hi = a < b ? b : a;
    a = up ? lo : hi;  b = up ? hi : lo;
}
__device__ __forceinline__ void writeOut(u64 key, int e, int M,
                                         const float* __restrict__ det_boxes) {
    if (e < M) {
        int orig = (int)(key & 0xFFFFFFFFu);
        g_sortedIdx[e] = orig;
        float4 b = ((const float4*)det_boxes)[orig];   // [y1, x1, y2, x2]
        g_sortedBox[e] = b;
        g_areaArr[e] = (b.w - b.y) * (b.z - b.x);      // (x2-x1)*(y2-y1)
    }
}

__global__ __launch_bounds__(1024, 1)
void kPrep(const float* __restrict__ roi_scores,
           const float* __restrict__ det_boxes) {
    extern __shared__ u64 sKeys[];                     // CAP entries = 32 KB
    __shared__ int s_cnt;
    const int tid = threadIdx.x;
    const u64 PADK = 0xFFFFFFFFFFFFFFFFULL;
    if (tid == 0) s_cnt = 0;
    __syncthreads();

    for (int i = tid; i < N_BOX; i += 1024) {
        float s = roi_scores[i];
        if (s >= MIN_RPN) {
            int p = atomicAdd(&s_cnt, 1);
            if (p < CAP)
                sKeys[p] = ((u64)(0xFFFFFFFFu - __float_as_uint(s)) << 32) | (unsigned)i;
        }
    }
    __syncthreads();
    const int M = min(s_cnt, CAP);
    if (tid == 0) g_M = M;

    if (M <= 2048) {
        // ---------- fast path: P=2048, hybrid shared/register bitonic ----------
        for (int t = M + tid; t < 2048; t += 1024) sKeys[t] = PADK;
        __syncthreads();
        u64 a = sKeys[2 * tid], b = sKeys[2 * tid + 1];

        #pragma unroll
        for (int k = 2; k <= 32; k <<= 1) {
            bool up = ((tid & (k >> 1)) == 0);
            for (int j = k >> 1; j >= 2; j >>= 1) {
                a = shflCmp(a, j >> 1, up, tid);
                b = shflCmp(b, j >> 1, up, tid);
            }
            cmpSwapReg(a, b, up);
        }
        for (int k = 64; k <= 2048; k <<= 1) {
            sKeys[2 * tid] = a; sKeys[2 * tid + 1] = b;
            __syncthreads();
            for (int j = k >> 1; j >= 32; j >>= 1) {
                #pragma unroll
                for (int r = 0; r < 2; ++r) {
                    int t2 = tid + r * 1024;
                    int ixj = t2 ^ j;
                    if (ixj > t2) {
                        bool up2 = ((t2 & k) == 0);
                        u64 x = sKeys[t2], y = sKeys[ixj];
                        if ((x > y) == up2) { sKeys[t2] = y; sKeys[ixj] = x; }
                    }
                }
                __syncthreads();
            }
            a = sKeys[2 * tid]; b = sKeys[2 * tid + 1];
            bool up = ((tid & (k >> 1)) == 0);
            #pragma unroll
            for (int j = 16; j >= 2; j >>= 1) {
                a = shflCmp(a, j >> 1, up, tid);
                b = shflCmp(b, j >> 1, up, tid);
            }
            cmpSwapReg(a, b, up);
        }
        writeOut(a, 2 * tid,     M, det_boxes);
        writeOut(b, 2 * tid + 1, M, det_boxes);
    } else {
        // ---------- generic fallback: shared-only bitonic up to P=4096 ----------
        int P = 2; while (P < M) P <<= 1;
        for (int t = M + tid; t < P; t += 1024) sKeys[t] = PADK;
        __syncthreads();
        for (int k = 2; k <= P; k <<= 1) {
            for (int j = k >> 1; j > 0; j >>= 1) {
                for (int t = tid; t < P; t += 1024) {
                    int ixj = t ^ j;
                    if (ixj > t) {
                        bool up = ((t & k) == 0);
                        u64 x = sKeys[t], y = sKeys[ixj];
                        if ((x > y) == up) { sKeys[t] = y; sKeys[ixj] = x; }
                    }
                }
                __syncthreads();
            }
        }
        for (int t = tid; t < M; t += 1024) writeOut(sKeys[t], t, M, det_boxes);
    }
}

// ================= kernel 2: triangular suppression bitmask (diag incl.), div only if overlap =================
__global__ void kMatrix() {
    const int M  = g_M;
    const int Mw = (M + 31) >> 5;
    const int total = M * Mw;
    const int stride = gridDim.x * blockDim.x;
    for (int it = blockIdx.x * blockDim.x + threadIdx.x; it < total; it += stride) {
        int i = it / Mw;
        int w = it - i * Mw;
        if (w < (i >> 5)) continue;          // words w >= i>>5; bits restricted to j > i
        float4 bi = g_sortedBox[i];
        float  ai = g_areaArr[i];
        unsigned bits = 0;
        int j0 = w * 32;
        int jend = min(32, M - j0);
        int jstart = (j0 <= i) ? (i - j0 + 1) : 0;   // diagonal word: only j > i
        for (int jj = jstart; jj < jend; ++jj) {
            float4 bj = g_sortedBox[j0 + jj];
            float iw = fmaxf(0.0f, fminf(bi.w, bj.w) - fmaxf(bi.y, bj.y));
            float ih = fmaxf(0.0f, fminf(bi.z, bj.z) - fmaxf(bi.x, bj.x));
            float inter = iw * ih;
            // inter == 0 -> iou == 0 exactly (denom > 0) -> never > 0.6: skip the division
            if (inter > 0.0f) {
                float iou = inter / (ai + g_areaArr[j0 + jj] - inter + 1e-12f);
                if (iou > NMS_THRESH) bits |= (1u << jj);
            }
        }
        g_mat[(size_t)i * RW + w] = bits;
    }
}

// ================= kernel 3: 64-box-chunk scan + select + GEMM + sort + outputs =================
#define NTHR 512

__global__ __launch_bounds__(NTHR, 1)
void kFinal(const float* __restrict__ roi_boxes,
            const float* __restrict__ det_boxes,
            const float* __restrict__ vis,
            const float* __restrict__ img_info,
            const float* __restrict__ txt,
            float* __restrict__ out) {
    __shared__ unsigned s_removed[RW];
    __shared__ unsigned s_keepw[RW];
    __shared__ unsigned s_flags[FLAG_WORDS];
    __shared__ int      s_scan[FLAG_WORDS];
    __shared__ int      s_wsum[16];
    __shared__ unsigned s_kmlo, s_kmhi;
    __shared__ int      s_cnt;
    __shared__ int      s_count;
    __shared__ int      s_selidx[KSEL];
    __shared__ float    S[KSEL][NUM_CATS];
    __shared__ float    s_key[KSEL];
    __shared__ int      s_src[KSEL];
    __shared__ unsigned char s_fgv[KSEL];

    const int tid  = threadIdx.x;
    const int lane = tid & 31;
    const int wid  = tid >> 5;          // 16 warps
    const int M    = g_M;
    const int Mw   = (M + 31) >> 5;
    const int Mc   = (M + 63) >> 6;     // 64-box chunks

    for (int t = tid; t < RW; t += NTHR) { s_removed[t] = 0; s_keepw[t] = 0; }
    for (int t = tid; t < FLAG_WORDS; t += NTHR) s_flags[t] = 0;
    if (tid == 0) s_cnt = 0;
    __syncthreads();

    // ---- chunked greedy NMS scan: warp0 resolves 64 boxes in registers, 16 warps propagate ----
    {
        // warp0's diag registers for current chunk (lane holds its own rows' words)
        unsigned d0lo = 0, d0hi = 0, d1hi = 0;
        if (wid == 0 && Mc > 0) {
            int r0 = lane, r1 = 32 + lane;
            if (r0 < M) { d0lo = g_mat[(size_t)r0 * RW + 0];
                          if (1 < Mw) d0hi = g_mat[(size_t)r0 * RW + 1]; }
            if (r1 < M && 1 < Mw) d1hi = g_mat[(size_t)r1 * RW + 1];
        }

        for (int c = 0; c < Mc; ++c) {
            const int base = c * 64;
            const int lim  = M - base;                 // >0

            if (wid == 0) {
                unsigned valid0 = (lim >= 32) ? 0xFFFFFFFFu : ((1u << lim) - 1u);
                unsigned valid1 = (lim >= 64) ? 0xFFFFFFFFu
                                 : (lim > 32) ? ((1u << (lim - 32)) - 1u) : 0u;
                unsigned avail0 = valid0 & ~s_removed[2 * c];
                unsigned avail1 = valid1 & ~s_removed[2 * c + 1];
                unsigned kmlo = 0, kmhi = 0;
                int cnt = s_cnt;

                #pragma unroll
                for (int i = 0; i < 32; ++i) {
                    unsigned rlo = __shfl_sync(0xffffffffu, d0lo, i);
                    unsigned rhi = __shfl_sync(0xffffffffu, d0hi, i);
                    if (((avail0 >> i) & 1u) && cnt < MAX_DETS) {
                        kmlo |= 1u << i; ++cnt;
                        avail0 &= ~rlo; avail1 &= ~rhi;
                    }
                }
                #pragma unroll
                for (int i = 0; i < 32; ++i) {
                    unsigned rhi = __shfl_sync(0xffffffffu, d1hi, i);
                    if (((avail1 >> i) & 1u) && cnt < MAX_DETS) {
                        kmhi |= 1u << i; ++cnt;
                        avail1 &= ~rhi;
                    }
                }
                if (lane == 0) {
                    s_keepw[2 * c] = kmlo;
                    if (2 * c + 1 < Mw) s_keepw[2 * c + 1] = kmhi;
                    s_kmlo = kmlo; s_kmhi = kmhi; s_cnt = cnt;
                }
                // prefetch next chunk's diag (latency hidden by cross phase + barrier)
                d0lo = d0hi = d1hi = 0;
                if (c + 1 < Mc) {
                    int nb = (c + 1) * 64;
                    int r0 = nb + lane, r1 = nb + 32 + lane;
                    int w0 = 2 * c + 2, w1 = 2 * c + 3;
                    if (r0 < M) { d0lo = g_mat[(size_t)r0 * RW + w0];
                                  if (w1 < Mw) d0hi = g_mat[(size_t)r0 * RW + w1]; }
                    if (r1 < M && w1 < Mw) d1hi = g_mat[(size_t)r1 * RW + w1];
                }
            }
            __syncthreads();

            const unsigned kmlo = s_kmlo, kmhi = s_kmhi;
            const int stop = (s_cnt >= MAX_DETS);      // read strictly between the two barriers
            if (kmlo | kmhi) {
                for (int w = 2 * c + 2 + wid; w < Mw; w += 16) {
                    unsigned v = 0;
                    if ((kmlo >> lane) & 1u) v |= g_mat[(size_t)(base + lane) * RW + w];
                    if ((kmhi >> lane) & 1u) v |= g_mat[(size_t)(base + 32 + lane) * RW + w];
                    unsigned red = __reduce_or_sync(0xffffffffu, v);
                    if (lane == 0 && red) s_removed[w] |= red;
                }
            }
            __syncthreads();
            if (stop) break;                           // uniform; later s_keepw words stay 0
        }
    }

    // ---- valid flags on ORIGINAL indices ----
    const float sy = img_info[4];    // image_info[2][0]
    const float sx = img_info[5];    // image_info[2][1]
    for (int t = tid; t < M; t += NTHR) {
        if ((s_keepw[t >> 5] >> (t & 31)) & 1u) {
            int orig = g_sortedIdx[t];
            float4 rb = ((const float4*)roi_boxes)[orig];
            bool allz = (rb.x == 0.f && rb.y == 0.f && rb.z == 0.f && rb.w == 0.f);
            float4 db = g_sortedBox[t];
            float area = (db.z / sy - db.x / sy) * (db.w / sx - db.y / sx);
            if (!allz && area > MIN_AREA)
                atomicOr(&s_flags[orig >> 5], 1u << (orig & 31));
        }
    }
    __syncthreads();

    // ---- inclusive prefix scan over 512 popcounts (warp shuffles) ----
    {
        int v = __popc(s_flags[tid]);
        #pragma unroll
        for (int off = 1; off < 32; off <<= 1) {
            int n = __shfl_up_sync(0xffffffff, v, off);
            if (lane >= off) v += n;
        }
        if (lane == 31) s_wsum[wid] = v;
        __syncthreads();
        if (wid == 0 && lane < 16) {
            int w = s_wsum[lane];
            #pragma unroll
            for (int off = 1; off < 16; off <<= 1) {
                int n = __shfl_up_sync(0x0000ffff, w, off);
                if (lane >= off) w += n;
            }
            s_wsum[lane] = w;
        }
        __syncthreads();
        int basew = (wid > 0) ? s_wsum[wid - 1] : 0;
        s_scan[tid] = basew + v;                         // inclusive
        if (tid == 0) s_count = s_wsum[15];
    }
    if (tid < KSEL) s_selidx[tid] = 0;                   // jnp.nonzero fill_value = 0
    __syncthreads();
    {
        int excl = s_scan[tid] - __popc(s_flags[tid]);
        if (excl < KSEL) {
            unsigned f = s_flags[tid];
            int r = excl;
            while (f && r < KSEL) {
                int b = __ffs(f) - 1; f &= f - 1;
                s_selidx[r] = tid * 32 + b;
                ++r;
            }
        }
    }
    __syncthreads();

    // ---- GEMM: S[25][65] = vis[idx] @ txt^T  (warp-per-2-rows, K split across lanes) ----
    if (wid < 13) {
        const int r0 = 2 * wid;
        const int r1 = r0 + 1;
        const bool has1 = (r1 < KSEL);
        const float4* v0 = (const float4*)(vis + (size_t)s_selidx[r0] * FEAT);
        const float4* v1 = (const float4*)(vis + (size_t)s_selidx[has1 ? r1 : r0] * FEAT);
        float4 a0[4], a1[4];
        #pragma unroll
        for (int q = 0; q < 4; ++q) {
            a0[q] = v0[q * 32 + lane];                   // coalesced: 32 lanes = 512B
            a1[q] = v1[q * 32 + lane];
        }
        for (int cc = 0; cc < NUM_CATS; ++cc) {
            const float4* tf = (const float4*)(txt + (size_t)cc * FEAT);
            float p0 = 0.f, p1 = 0.f;
            #pragma unroll
            for (int q = 0; q < 4; ++q) {
                float4 b = tf[q * 32 + lane];            // coalesced
                p0 += a0[q].x * b.x + a0[q].y * b.y + a0[q].z * b.z + a0[q].w * b.w;
                p1 += a1[q].x * b.x + a1[q].y * b.y + a1[q].z * b.z + a1[q].w * b.w;
            }
            #pragma unroll
            for (int off = 16; off; off >>= 1) {
                p0 += __shfl_xor_sync(0xffffffff, p0, off);
                p1 += __shfl_xor_sync(0xffffffff, p1, off);
            }
            if (lane == 0) {
                S[r0][cc] = p0;
                if (has1) S[r1][cc] = p1;
            }
        }
    }
    __syncthreads();

    // ---- per-row max / argmax, fg, sort key ----
    if (tid < KSEL) {
        float mx = S[tid][0]; int am = 0;
        for (int cc = 1; cc < NUM_CATS; ++cc) {
            float v = S[tid][cc];
            if (v > mx) { mx = v; am = cc; }
        }
        bool rv = tid < min(s_count, KSEL);
        bool fg = rv && (am != 0);
        s_fgv[tid] = fg ? 1 : 0;
        s_key[tid] = fg ? mx : __int_as_float(0xff800000);   // -inf
    }
    __syncthreads();

    // ---- stable descending argsort via rank ----
    if (tid < KSEL) {
        float k = s_key[tid];
        int rank = 0;
        for (int j = 0; j < KSEL; ++j) {
            float kj = s_key[j];
            if (kj > k || (kj == k && j < tid)) ++rank;
        }
        s_src[rank] = tid;
    }
    __syncthreads();

    // ---- outputs: scores (25x64) | bboxes (25x4) | mask (25) ----
    for (int p = tid; p < KSEL * (NUM_CATS - 1); p += NTHR) {
        int row = p / (NUM_CATS - 1), cc = p - row * (NUM_CATS - 1);
        int s = s_src[row];
        out[p] = s_fgv[s] ? S[s][cc + 1] : 0.f;
    }
    if (tid < KSEL) {
        int s = s_src[tid];
        bool m = s_fgv[s] != 0;
        float4 db = ((const float4*)det_boxes)[s_selidx[s]];
        float xmin = db.y / sx, ymin = db.x / sy, xmax = db.w / sx, ymax = db.z / sy;
        float* o = out + KSEL * (NUM_CATS - 1) + tid * 4;
        o[0] = m ? xmin : 0.f;
        o[1] = m ? ymin : 0.f;
        o[2] = m ? xmax : 0.f;
        o[3] = m ? ymax : 0.f;
        out[KSEL * (NUM_CATS - 1) + KSEL * 4 + tid] = m ? 1.f : 0.f;
    }
}

// ---------------- launch ----------------
extern "C" void kernel_launch(void* const* d_in, const int* in_sizes, int n_in,
                              void* d_out, int out_size) {
    const float* roi_boxes  = (const float*)d_in[0];
    const float* roi_scores = (const float*)d_in[1];
    const float* det_boxes  = (const float*)d_in[2];
    /* d_in[3]: detection_masks — unused by reference outputs */
    const float* vis        = (const float*)d_in[4];
    const float* img_info   = (const float*)d_in[5];
    const float* txt        = (const float*)d_in[6];
    float* out = (float*)d_out;

    kPrep<<<1, 1024, CAP * 8>>>(roi_scores, det_boxes);
    kMatrix<<<512, 256>>>();
    kFinal<<<1, NTHR>>>(roi_boxes, det_boxes, vis, img_info, txt, out);
}

// round 10
// speedup vs baseline: 2.3100x; 1.0994x over previous
#include <cuda_runtime.h>
#include <cstdint>

#define N_BOX 16384
#define FEAT 512
#define NUM_CATS 65
#define KSEL 25
#define MAX_DETS 1000
#define NMS_THRESH 0.6f
#define MIN_RPN 0.9f
#define MIN_AREA 220.0f
#define FLAG_WORDS 512      /* 16384/32 */
#define CAP 4096            /* hard cap on boxes passing score gate */
#define RW  (CAP / 32)      /* 128 words per matrix row */

#define NBUCK 4096
#define BUCK_SHIFT 9
#define BUCK_BASE 0x3F666666u   /* bits of 0.9f; scores in [0.9,1) share one exponent */

// ---------------- device scratch ----------------
__device__ int    g_M;
__device__ int    g_sortedIdx[CAP];
__device__ float4 g_sortedBox[CAP];
__device__ float  g_areaArr[CAP];
__device__ unsigned long long g_keys[CAP];     // sort keys (global: keeps kPrep smem < 48KB)
__device__ unsigned g_mat[(size_t)CAP * RW];   // suppression bitmask, words w >= i>>5 (bits j>i)

typedef unsigned long long u64;

// ================= kernel 1: compact + counting sort + gather =================
__global__ __launch_bounds__(1024, 1)
void kPrep(const float* __restrict__ roi_scores,
           const float* __restrict__ det_boxes) {
    __shared__ int sBase[NBUCK];               // 16 KB
    __shared__ int sCur[NBUCK];                // 16 KB (count, then cursor)
    __shared__ int s_wsum[32];
    __shared__ int s_M;

    const int tid  = threadIdx.x;
    const int lane = tid & 31;
    const int wid  = tid >> 5;                 // 32 warps

    #pragma unroll
    for (int k = 0; k < 4; ++k) sCur[tid * 4 + k] = 0;
    __syncthreads();

    // ---- phase 1: histogram of passing scores ----
    #pragma unroll
    for (int it = 0; it < N_BOX / 1024; ++it) {
        int i = tid + it * 1024;
        float s = roi_scores[i];
        if (s >= MIN_RPN) {
            unsigned bits = __float_as_uint(s);
            int b = min((int)((bits - BUCK_BASE) >> BUCK_SHIFT), NBUCK - 1);
            atomicAdd(&sCur[b], 1);
        }
    }
    __syncthreads();

    // ---- phase 2: exclusive scan in DESCENDING bucket order ----
    {
        int c[4], sum = 0;
        #pragma unroll
        for (int k = 0; k < 4; ++k) {
            int b = NBUCK - 1 - (tid * 4 + k);
            c[k] = sCur[b];
            sum += c[k];
        }
        int v = sum;
        #pragma unroll
        for (int off = 1; off < 32; off <<= 1) {
            int n = __shfl_up_sync(0xffffffffu, v, off);
            if (lane >= off) v += n;
        }
        if (lane == 31) s_wsum[wid] = v;
        __syncthreads();
        if (wid == 0) {
            int w = s_wsum[lane];
            #pragma unroll
            for (int off = 1; off < 32; off <<= 1) {
                int n = __shfl_up_sync(0xffffffffu, w, off);
                if (lane >= off) w += n;
            }
            s_wsum[lane] = w;
        }
        __syncthreads();
        int base = ((wid > 0) ? s_wsum[wid - 1] : 0) + (v - sum);  // exclusive for this thread
        #pragma unroll
        for (int k = 0; k < 4; ++k) {
            int b = NBUCK - 1 - (tid * 4 + k);
            sBase[b] = base;
            base += c[k];
        }
        if (tid == 0) s_M = min(s_wsum[31], CAP);
    }
    __syncthreads();
    const int M = s_M;
    if (tid == 0) g_M = M;
    #pragma unroll
    for (int k = 0; k < 4; ++k) {
        int b = tid * 4 + k;
        sCur[b] = sBase[b];                    // cursor = base
    }
    __syncthreads();

    // ---- phase 3: scatter keys to (nearly) sorted positions ----
    #pragma unroll
    for (int it = 0; it < N_BOX / 1024; ++it) {
        int i = tid + it * 1024;
        float s = roi_scores[i];
        if (s >= MIN_RPN) {
            unsigned bits = __float_as_uint(s);
            int b = min((int)((bits - BUCK_BASE) >> BUCK_SHIFT), NBUCK - 1);
            int pos = atomicAdd(&sCur[b], 1);
            if (pos < CAP)
                g_keys[pos] = ((u64)(0xFFFFFFFFu - bits) << 32) | (unsigned)i;
        }
    }
    __syncthreads();   // also fences block-visible global writes

    // ---- phase 4: fixup multi-occupancy buckets (exact (score desc, idx asc) order) ----
    #pragma unroll
    for (int k = 0; k < 4; ++k) {
        int b = tid * 4 + k;
        int st = sBase[b];
        int en = (b > 0) ? sBase[b - 1] : M;   // descending layout: next-lower bucket's base
        if (en > CAP) en = CAP;
        if (en - st > 1) {
            for (int a = st + 1; a < en; ++a) { // insertion sort (ascending keys)
                u64 key = g_keys[a];
                int p = a - 1;
                while (p >= st && g_keys[p] > key) { g_keys[p + 1] = g_keys[p]; --p; }
                g_keys[p + 1] = key;
            }
        }
    }
    __syncthreads();

    // ---- phase 5: gather boxes in sorted order ----
    for (int t = tid; t < M; t += 1024) {
        u64 key = g_keys[t];
        int orig = (int)(key & 0xFFFFFFFFu);
        g_sortedIdx[t] = orig;
        float4 b = ((const float4*)det_boxes)[orig];   // [y1, x1, y2, x2]
        g_sortedBox[t] = b;
        g_areaArr[t] = (b.w - b.y) * (b.z - b.x);      // (x2-x1)*(y2-y1)
    }
}

// ================= kernel 2: triangular suppression bitmask (diag incl.), div only if overlap =================
__global__ void kMatrix() {
    const int M  = g_M;
    const int Mw = (M + 31) >> 5;
    const int total = M * Mw;
    const int stride = gridDim.x * blockDim.x;
    for (int it = blockIdx.x * blockDim.x + threadIdx.x; it < total; it += stride) {
        int i = it / Mw;
        int w = it - i * Mw;
        if (w < (i >> 5)) continue;          // words w >= i>>5; bits restricted to j > i
        float4 bi = g_sortedBox[i];
        float  ai = g_areaArr[i];
        unsigned bits = 0;
        int j0 = w * 32;
        int jend = min(32, M - j0);
        int jstart = (j0 <= i) ? (i - j0 + 1) : 0;   // diagonal word: only j > i
        for (int jj = jstart; jj < jend; ++jj) {
            float4 bj = g_sortedBox[j0 + jj];
            float iw = fmaxf(0.0f, fminf(bi.w, bj.w) - fmaxf(bi.y, bj.y));
            float ih = fmaxf(0.0f, fminf(bi.z, bj.z) - fmaxf(bi.x, bj.x));
            float inter = iw * ih;
            // inter == 0 -> iou == 0 exactly (denom > 0) -> never > 0.6: skip the division
            if (inter > 0.0f) {
                float iou = inter / (ai + g_areaArr[j0 + jj] - inter + 1e-12f);
                if (iou > NMS_THRESH) bits |= (1u << jj);
            }
        }
        g_mat[(size_t)i * RW + w] = bits;
    }
}

// ================= kernel 3: 64-box-chunk scan + select + GEMM + sort + outputs =================
#define NTHR 512

__global__ __launch_bounds__(NTHR, 1)
void kFinal(const float* __restrict__ roi_boxes,
            const float* __restrict__ det_boxes,
            const float* __restrict__ vis,
            const float* __restrict__ img_info,
            const float* __restrict__ txt,
            float* __restrict__ out) {
    __shared__ unsigned s_removed[RW];
    __shared__ unsigned s_keepw[RW];
    __shared__ unsigned s_flags[FLAG_WORDS];
    __shared__ int      s_scan[FLAG_WORDS];
    __shared__ int      s_wsum[16];
    __shared__ unsigned s_kmlo, s_kmhi;
    __shared__ int      s_cnt;
    __shared__ int      s_count;
    __shared__ int      s_selidx[KSEL];
    __shared__ float    S[KSEL][NUM_CATS];
    __shared__ float    s_key[KSEL];
    __shared__ int      s_src[KSEL];
    __shared__ unsigned char s_fgv[KSEL];

    const int tid  = threadIdx.x;
    const int lane = tid & 31;
    const int wid  = tid >> 5;          // 16 warps
    const int M    = g_M;
    const int Mw   = (M + 31) >> 5;
    const int Mc   = (M + 63) >> 6;     // 64-box chunks

    for (int t = tid; t < RW; t += NTHR) { s_removed[t] = 0; s_keepw[t] = 0; }
    for (int t = tid; t < FLAG_WORDS; t += NTHR) s_flags[t] = 0;
    if (tid == 0) s_cnt = 0;
    __syncthreads();

    // ---- chunked greedy NMS scan: warp0 resolves 64 boxes in registers, 16 warps propagate ----
    {
        // warp0's diag registers for current chunk (lane holds its own rows' words)
        unsigned d0lo = 0, d0hi = 0, d1hi = 0;
        if (wid == 0 && Mc > 0) {
            int r0 = lane, r1 = 32 + lane;
            if (r0 < M) { d0lo = g_mat[(size_t)r0 * RW + 0];
                          if (1 < Mw) d0hi = g_mat[(size_t)r0 * RW + 1]; }
            if (r1 < M && 1 < Mw) d1hi = g_mat[(size_t)r1 * RW + 1];
        }

        for (int c = 0; c < Mc; ++c) {
            const int base = c * 64;
            const int lim  = M - base;                 // >0

            if (wid == 0) {
                unsigned valid0 = (lim >= 32) ? 0xFFFFFFFFu : ((1u << lim) - 1u);
                unsigned valid1 = (lim >= 64) ? 0xFFFFFFFFu
                                 : (lim > 32) ? ((1u << (lim - 32)) - 1u) : 0u;
                unsigned avail0 = valid0 & ~s_removed[2 * c];
                unsigned avail1 = valid1 & ~s_removed[2 * c + 1];
                unsigned kmlo = 0, kmhi = 0;
                int cnt = s_cnt;

                #pragma unroll
                for (int i = 0; i < 32; ++i) {
                    unsigned rlo = __shfl_sync(0xffffffffu, d0lo, i);
                    unsigned rhi = __shfl_sync(0xffffffffu, d0hi, i);
                    if (((avail0 >> i) & 1u) && cnt < MAX_DETS) {
                        kmlo |= 1u << i; ++cnt;
                        avail0 &= ~rlo; avail1 &= ~rhi;
                    }
                }
                #pragma unroll
                for (int i = 0; i < 32; ++i) {
                    unsigned rhi = __shfl_sync(0xffffffffu, d1hi, i);
                    if (((avail1 >> i) & 1u) && cnt < MAX_DETS) {
                        kmhi |= 1u << i; ++cnt;
                        avail1 &= ~rhi;
                    }
                }
                if (lane == 0) {
                    s_keepw[2 * c] = kmlo;
                    if (2 * c + 1 < Mw) s_keepw[2 * c + 1] = kmhi;
                    s_kmlo = kmlo; s_kmhi = kmhi; s_cnt = cnt;
                }
                // prefetch next chunk's diag (latency hidden by cross phase + barrier)
                d0lo = d0hi = d1hi = 0;
                if (c + 1 < Mc) {
                    int nb = (c + 1) * 64;
                    int r0 = nb + lane, r1 = nb + 32 + lane;
                    int w0 = 2 * c + 2, w1 = 2 * c + 3;
                    if (r0 < M) { d0lo = g_mat[(size_t)r0 * RW + w0];
                                  if (w1 < Mw) d0hi = g_mat[(size_t)r0 * RW + w1]; }
                    if (r1 < M && w1 < Mw) d1hi = g_mat[(size_t)r1 * RW + w1];
                }
            }
            __syncthreads();

            const unsigned kmlo = s_kmlo, kmhi = s_kmhi;
            const int stop = (s_cnt >= MAX_DETS);      // read strictly between the two barriers
            if (kmlo | kmhi) {
                for (int w = 2 * c + 2 + wid; w < Mw; w += 16) {
                    unsigned v = 0;
                    if ((kmlo >> lane) & 1u) v |= g_mat[(size_t)(base + lane) * RW + w];
                    if ((kmhi >> lane) & 1u) v |= g_mat[(size_t)(base + 32 + lane) * RW + w];
                    unsigned red = __reduce_or_sync(0xffffffffu, v);
                    if (lane == 0 && red) s_removed[w] |= red;
                }
            }
            __syncthreads();
            if (stop) break;                           // uniform; later s_keepw words stay 0
        }
    }

    // ---- valid flags on ORIGINAL indices ----
    const float sy = img_info[4];    // image_info[2][0]
    const float sx = img_info[5];    // image_info[2][1]
    for (int t = tid; t < M; t += NTHR) {
        if ((s_keepw[t >> 5] >> (t & 31)) & 1u) {
            int orig = g_sortedIdx[t];
            float4 rb = ((const float4*)roi_boxes)[orig];
            bool allz = (rb.x == 0.f && rb.y == 0.f && rb.z == 0.f && rb.w == 0.f);
            float4 db = g_sortedBox[t];
            float area = (db.z / sy - db.x / sy) * (db.w / sx - db.y / sx);
            if (!allz && area > MIN_AREA)
                atomicOr(&s_flags[orig >> 5], 1u << (orig & 31));
        }
    }
    __syncthreads();

    // ---- inclusive prefix scan over 512 popcounts (warp shuffles) ----
    {
        int v = __popc(s_flags[tid]);
        #pragma unroll
        for (int off = 1; off < 32; off <<= 1) {
            int n = __shfl_up_sync(0xffffffff, v, off);
            if (lane >= off) v += n;
        }
        if (lane == 31) s_wsum[wid] = v;
        __syncthreads();
        if (wid == 0 && lane < 16) {
            int w = s_wsum[lane];
            #pragma unroll
            for (int off = 1; off < 16; off <<= 1) {
                int n = __shfl_up_sync(0x0000ffff, w, off);
                if (lane >= off) w += n;
            }
            s_wsum[lane] = w;
        }
        __syncthreads();
        int basew = (wid > 0) ? s_wsum[wid - 1] : 0;
        s_scan[tid] = basew + v;                         // inclusive
        if (tid == 0) s_count = s_wsum[15];
    }
    if (tid < KSEL) s_selidx[tid] = 0;                   // jnp.nonzero fill_value = 0
    __syncthreads();
    {
        int excl = s_scan[tid] - __popc(s_flags[tid]);
        if (excl < KSEL) {
            unsigned f = s_flags[tid];
            int r = excl;
            while (f && r < KSEL) {
                int b = __ffs(f) - 1; f &= f - 1;
                s_selidx[r] = tid * 32 + b;
                ++r;
            }
        }
    }
    __syncthreads();

    // ---- GEMM: S[25][65] = vis[idx] @ txt^T  (warp-per-2-rows, K split across lanes) ----
    if (wid < 13) {
        const int r0 = 2 * wid;
        const int r1 = r0 + 1;
        const bool has1 = (r1 < KSEL);
        const float4* v0 = (const float4*)(vis + (size_t)s_selidx[r0] * FEAT);
        const float4* v1 = (const float4*)(vis + (size_t)s_selidx[has1 ? r1 : r0] * FEAT);
        float4 a0[4], a1[4];
        #pragma unroll
        for (int q = 0; q < 4; ++q) {
            a0[q] = v0[q * 32 + lane];                   // coalesced: 32 lanes = 512B
            a1[q] = v1[q * 32 + lane];
        }
        for (int cc = 0; cc < NUM_CATS; ++cc) {
            const float4* tf = (const float4*)(txt + (size_t)cc * FEAT);
            float p0 = 0.f, p1 = 0.f;
            #pragma unroll
            for (int q = 0; q < 4; ++q) {
                float4 b = tf[q * 32 + lane];            // coalesced
                p0 += a0[q].x * b.x + a0[q].y * b.y + a0[q].z * b.z + a0[q].w * b.w;
                p1 += a1[q].x * b.x + a1[q].y * b.y + a1[q].z * b.z + a1[q].w * b.w;
            }
            #pragma unroll
            for (int off = 16; off; off >>= 1) {
                p0 += __shfl_xor_sync(0xffffffff, p0, off);
                p1 += __shfl_xor_sync(0xffffffff, p1, off);
            }
            if (lane == 0) {
                S[r0][cc] = p0;
                if (has1) S[r1][cc] = p1;
            }
        }
    }
    __syncthreads();

    // ---- per-row max / argmax, fg, sort key ----
    if (tid < KSEL) {
        float mx = S[tid][0]; int am = 0;
        for (int cc = 1; cc < NUM_CATS; ++cc) {
            float v = S[tid][cc];
            if (v > mx) { mx = v; am = cc; }
        }
        bool rv = tid < min(s_count, KSEL);
        bool fg = rv && (am != 0);
        s_fgv[tid] = fg ? 1 : 0;
        s_key[tid] = fg ? mx : __int_as_float(0xff800000);   // -inf
    }
    __syncthreads();

    // ---- stable descending argsort via rank ----
    if (tid < KSEL) {
        float k = s_key[tid];
        int rank = 0;
        for (int j = 0; j < KSEL; ++j) {
            float kj = s_key[j];
            if (kj > k || (kj == k && j < tid)) ++rank;
        }
        s_src[rank] = tid;
    }
    __syncthreads();

    // ---- outputs: scores (25x64) | bboxes (25x4) | mask (25) ----
    for (int p = tid; p < KSEL * (NUM_CATS - 1); p += NTHR) {
        int row = p / (NUM_CATS - 1), cc = p - row * (NUM_CATS - 1);
        int s = s_src[row];
        out[p] = s_fgv[s] ? S[s][cc + 1] : 0.f;
    }
    if (tid < KSEL) {
        int s = s_src[tid];
        bool m = s_fgv[s] != 0;
        float4 db = ((const float4*)det_boxes)[s_selidx[s]];
        float xmin = db.y / sx, ymin = db.x / sy, xmax = db.w / sx, ymax = db.z / sy;
        float* o = out + KSEL * (NUM_CATS - 1) + tid * 4;
        o[0] = m ? xmin : 0.f;
        o[1] = m ? ymin : 0.f;
        o[2] = m ? xmax : 0.f;
        o[3] = m ? ymax : 0.f;
        out[KSEL * (NUM_CATS - 1) + KSEL * 4 + tid] = m ? 1.f : 0.f;
    }
}

// ---------------- launch ----------------
extern "C" void kernel_launch(void* const* d_in, const int* in_sizes, int n_in,
                              void* d_out, int out_size) {
    const float* roi_boxes  = (const float*)d_in[0];
    const float* roi_scores = (const float*)d_in[1];
    const float* det_boxes  = (const float*)d_in[2];
    /* d_in[3]: detection_masks — unused by reference outputs */
    const float* vis        = (const float*)d_in[4];
    const float* img_info   = (const float*)d_in[5];
    const float* txt        = (const float*)d_in[6];
    float* out = (float*)d_out;

    kPrep<<<1, 1024>>>(roi_scores, det_boxes);
    kMatrix<<<512, 256>>>();
    kFinal<<<1, NTHR>>>(roi_boxes, det_boxes, vis, img_info, txt, out);
}